// round 12
// baseline (speedup 1.0000x reference)
#include <cuda_runtime.h>
#include <cuda_fp16.h>

#define BB 2
#define CC 8
#define HH 512
#define WW 1024
#define OC 8
#define KY 3
#define KX 3
#define KK (KY*KX)
#define HW (HH*WW)

// fp16 transposed input: [b][pix] -> 8 channels packed in 16 bytes.
__device__ __align__(16) uint4 g_h[(size_t)BB * HW];
// staging for weight relayout [k][c][o]
__device__ __align__(16) float g_wstage[KK * CC * OC];

__constant__ __align__(16) float c_ws[KK * CC * OC]; // [k][c][o]
__constant__ __align__(16) float c_sb[OC];

// 4 pixels per thread: 8x LDG.128 (one float4 per channel) + 4x STG.128.
__global__ __launch_bounds__(256) void transpose_h4(const float* __restrict__ x) {
    int idx4 = blockIdx.x * 256 + threadIdx.x;   // over B*HW/4
    if (idx4 >= BB * HW / 4) return;
    int b = idx4 >> 17;                          // /(HW/4)
    int hw4 = idx4 & (HW / 4 - 1);
    const float4* xp = reinterpret_cast<const float4*>(x + (size_t)b * CC * HW) + hw4;
    float4 ch[CC];
#pragma unroll
    for (int c = 0; c < CC; c++) ch[c] = xp[c * (HW / 4)];

    uint4* dst = &g_h[(size_t)b * HW + hw4 * 4];
#pragma unroll
    for (int j = 0; j < 4; j++) {
        float p[CC];
        p[0] = (&ch[0].x)[j]; p[1] = (&ch[1].x)[j];
        p[2] = (&ch[2].x)[j]; p[3] = (&ch[3].x)[j];
        p[4] = (&ch[4].x)[j]; p[5] = (&ch[5].x)[j];
        p[6] = (&ch[6].x)[j]; p[7] = (&ch[7].x)[j];
        __half2 h0 = __floats2half2_rn(p[0], p[1]);
        __half2 h1 = __floats2half2_rn(p[2], p[3]);
        __half2 h2 = __floats2half2_rn(p[4], p[5]);
        __half2 h3 = __floats2half2_rn(p[6], p[7]);
        uint4 q;
        q.x = *reinterpret_cast<unsigned*>(&h0);
        q.y = *reinterpret_cast<unsigned*>(&h1);
        q.z = *reinterpret_cast<unsigned*>(&h2);
        q.w = *reinterpret_cast<unsigned*>(&h3);
        dst[j] = q;
    }
}

__global__ void repack_w(const float* __restrict__ wgt) {
    int i = threadIdx.x; // 0..575
    if (i >= KK * CC * OC) return;
    int k = i >> 6;
    int c = (i >> 3) & 7;
    int o = i & 7;
    g_wstage[i] = wgt[(o * CC + c) * KK + k];
}

// atan2 with single fast division + Cephes poly. ~1e-7 rad error.
// Returns exactly +/-0 when y == 0 and x > 0 (relied on for the fx==0 path).
__device__ __forceinline__ float fast_atan2f(float y, float x) {
    float ay = fabsf(y), ax = fabsf(x);
    float n = fminf(ay, ax), d = fmaxf(ay, ax);
    bool big = n > 0.4142135624f * d;
    float num = big ? (n - d) : n;
    float den = big ? (n + d) : d;
    float t = __fdividef(num, den);
    float z = t * t;
    float p = fmaf(fmaf(fmaf(8.05374449538e-2f, z, -1.38776856032e-1f), z,
                        1.99777106478e-1f), z, -3.33329491539e-1f);
    float r = fmaf(p * z, t, t);
    if (big) r += 0.78539816339744831f;
    if (ay > ax) r = 1.57079632679489662f - r;
    if (x < 0.0f) r = 3.14159265358979323f - r;
    return copysignf(r, y);
}

__device__ __forceinline__ unsigned long long dup_f32x2(float f) {
    unsigned long long r;
    asm("mov.b64 %0, {%1, %1};" : "=l"(r) : "f"(f));
    return r;
}

__device__ __forceinline__ void ffma2(unsigned long long& acc,
                                      unsigned long long a, unsigned long long b) {
    asm("fma.rn.f32x2 %0, %1, %2, %0;" : "+l"(acc) : "l"(a), "l"(b));
}

__device__ __forceinline__ __half2 u2h2(unsigned u) { return *reinterpret_cast<__half2*>(&u); }

// 4-tap bilinear over 8 fp16 channels -> 8 fp32
__device__ __forceinline__ void bilin4(uint4 A, uint4 B, uint4 C, uint4 D,
                                       __half2 w00, __half2 w01, __half2 w10, __half2 w11,
                                       float* v) {
    const __half2* a = reinterpret_cast<const __half2*>(&A);
    const __half2* b = reinterpret_cast<const __half2*>(&B);
    const __half2* c = reinterpret_cast<const __half2*>(&C);
    const __half2* d = reinterpret_cast<const __half2*>(&D);
#pragma unroll
    for (int j = 0; j < 4; j++) {
        __half2 t = __hmul2(a[j], w00);
        t = __hfma2(b[j], w01, t);
        t = __hfma2(c[j], w10, t);
        t = __hfma2(d[j], w11, t);
        float2 f = __half22float2(t);
        v[2 * j]     = f.x;
        v[2 * j + 1] = f.y;
    }
}

// 2-tap (y only): fx == 0 exact path
__device__ __forceinline__ void bilin2(uint4 A, uint4 B,
                                       __half2 wy0, __half2 wy1, float* v) {
    const __half2* a = reinterpret_cast<const __half2*>(&A);
    const __half2* b = reinterpret_cast<const __half2*>(&B);
#pragma unroll
    for (int j = 0; j < 4; j++) {
        __half2 t = __hfma2(b[j], wy1, __hmul2(a[j], wy0));
        float2 f = __half22float2(t);
        v[2 * j]     = f.x;
        v[2 * j + 1] = f.y;
    }
}

// direct convert of one pixel (exact center tap)
__device__ __forceinline__ void cvt8(uint4 A, float* v) {
    const __half2* a = reinterpret_cast<const __half2*>(&A);
#pragma unroll
    for (int j = 0; j < 4; j++) {
        float2 f = __half22float2(a[j]);
        v[2 * j]     = f.x;
        v[2 * j + 1] = f.y;
    }
}

__global__ __launch_bounds__(256, 4) void sconv_kernel(float* __restrict__ out) {
    constexpr float PI_F = 3.14159265358979323846f;
    __shared__ __align__(16) int4  s_i[8][KK];   // {mxi, y0*W, y1*W, axis_flag}
    __shared__ __align__(16) uint4 s_hw[8][KK];  // half2 weights {w00,w01,w10,w11}

    int lane = threadIdx.x;
    int ty = threadIdx.y;
    int tid = ty * 32 + lane;

    // Per-(h,k) warp-uniform geometry + packed bilinear weights.
    if (tid < 8 * KK) {
        int tr = tid / KK;
        int k = tid - tr * KK;
        int h = blockIdx.y * 8 + tr;
        const float scale = PI_F / (float)HH;
        const float gx_scale = (float)WW / (2.0f * PI_F);
        const float gy_scale = (float)HH / PI_F;
        float po = PI_F * ((float)(2 * h + 1) * (0.5f / HH));
        float sp, cp;
        sincosf(po, &sp, &cp);
        float dx = (float)(k % KX - 1) * scale;
        float dy = (float)(k / KX - 1) * scale;
        float alpha = fmaf(cp, dy, sp);
        float gamma = fmaf(-sp, dy, cp);
        float r = sqrtf(fmaf(alpha, alpha, dx * dx));
        float pol = fast_atan2f(r, gamma);
        float phi = fast_atan2f(dx, alpha);
        float gy = pol * gy_scale - 0.5f;
        int iy0 = __float2int_rd(gy);
        float fy = gy - (float)iy0;
        int iy1 = min(iy0 + 1, HH - 1);
        iy0 = max(iy0, 0);
        float phi_px = phi * gx_scale;
        int mxi = __float2int_rd(phi_px);
        float fx = phi_px - (float)mxi;
        int axis = (phi_px == 0.0f) ? 1 : 0;
        float wx0 = 1.0f - fx, fy0 = 1.0f - fy;
        __half2 h00 = __float2half2_rn(wx0 * fy0);
        __half2 h01 = __float2half2_rn(fx * fy0);
        __half2 h10 = __float2half2_rn(wx0 * fy);
        __half2 h11 = __float2half2_rn(fx * fy);
        s_i[tr][k] = make_int4(mxi, iy0 * WW, iy1 * WW, axis);
        uint4 hw;
        hw.x = *reinterpret_cast<unsigned*>(&h00);
        hw.y = *reinterpret_cast<unsigned*>(&h01);
        hw.z = *reinterpret_cast<unsigned*>(&h10);
        hw.w = *reinterpret_cast<unsigned*>(&h11);
        s_hw[tr][k] = hw;
    }
    __syncthreads();

    int w = blockIdx.x * 32 + lane;
    int h = blockIdx.y * 8 + ty;

    unsigned long long a0[4], a1[4];
    const unsigned long long* sbp = reinterpret_cast<const unsigned long long*>(c_sb);
#pragma unroll
    for (int j = 0; j < 4; j++) { a0[j] = sbp[j]; a1[j] = sbp[j]; }

    const ulonglong2* wsp = reinterpret_cast<const ulonglong2*>(c_ws);

#pragma unroll
    for (int k = 0; k < KK; k++) {
        float v0[8], v1[8];

        if (k == 4) {
            // center tap: exact identity sample
            int i = h * WW + w;
            cvt8(g_h[i], v0);
            cvt8(g_h[HW + i], v1);
        } else {
            int4 si = s_i[ty][k];
            uint4 hw = s_hw[ty][k];
            int ix0 = (w + si.x) & (WW - 1);
            bool axis = ((k == 1) || (k == 7)) && si.w;
            if (axis) {
                bilin2(g_h[si.y + ix0], g_h[si.z + ix0], u2h2(hw.x), u2h2(hw.z), v0);
                bilin2(g_h[HW + si.y + ix0], g_h[HW + si.z + ix0], u2h2(hw.x), u2h2(hw.z), v1);
            } else {
                int ix1 = (ix0 + 1) & (WW - 1);
                bilin4(g_h[si.y + ix0], g_h[si.y + ix1],
                       g_h[si.z + ix0], g_h[si.z + ix1],
                       u2h2(hw.x), u2h2(hw.y), u2h2(hw.z), u2h2(hw.w), v0);
                bilin4(g_h[HW + si.y + ix0], g_h[HW + si.y + ix1],
                       g_h[HW + si.z + ix0], g_h[HW + si.z + ix1],
                       u2h2(hw.x), u2h2(hw.y), u2h2(hw.z), u2h2(hw.w), v1);
            }
        }

        const ulonglong2* wk = wsp + k * 16;
#pragma unroll
        for (int c = 0; c < CC; c++) {
            ulonglong2 wa = wk[c * 2 + 0]; // (o0,o1),(o2,o3)
            ulonglong2 wb = wk[c * 2 + 1]; // (o4,o5),(o6,o7)
            unsigned long long vd0 = dup_f32x2(v0[c]);
            unsigned long long vd1 = dup_f32x2(v1[c]);
            ffma2(a0[0], vd0, wa.x);
            ffma2(a0[1], vd0, wa.y);
            ffma2(a0[2], vd0, wb.x);
            ffma2(a0[3], vd0, wb.y);
            ffma2(a1[0], vd1, wa.x);
            ffma2(a1[1], vd1, wa.y);
            ffma2(a1[2], vd1, wb.x);
            ffma2(a1[3], vd1, wb.y);
        }
    }

#pragma unroll
    for (int j = 0; j < 4; j++) {
        float l0, h0, l1, h1;
        asm("mov.b64 {%0, %1}, %2;" : "=f"(l0), "=f"(h0) : "l"(a0[j]));
        asm("mov.b64 {%0, %1}, %2;" : "=f"(l1), "=f"(h1) : "l"(a1[j]));
        int o = 2 * j;
        out[(size_t)((0 * OC + o) * HH + h) * WW + w]     = l0;
        out[(size_t)((0 * OC + o + 1) * HH + h) * WW + w] = h0;
        out[(size_t)((1 * OC + o) * HH + h) * WW + w]     = l1;
        out[(size_t)((1 * OC + o + 1) * HH + h) * WW + w] = h1;
    }
}

extern "C" void kernel_launch(void* const* d_in, const int* in_sizes, int n_in,
                              void* d_out, int out_size) {
    const float* x = (const float*)d_in[0];
    const float* wgt = (const float*)d_in[1];
    const float* bias = (const float*)d_in[2];
    float* out = (float*)d_out;

    int ngroups = BB * HW / 4;
    transpose_h4<<<(ngroups + 255) / 256, 256>>>(x);

    repack_w<<<1, KK * CC * OC>>>(wgt);

    // Resolve the staging buffer's real device address (query only — no alloc).
    void* wstage_dev = nullptr;
    cudaGetSymbolAddress(&wstage_dev, g_wstage);

    // D2D memcpy nodes (graph-capturable, allocation-free)
    cudaMemcpyToSymbolAsync(c_ws, wstage_dev, KK * CC * OC * sizeof(float), 0,
                            cudaMemcpyDeviceToDevice);
    cudaMemcpyToSymbolAsync(c_sb, bias, OC * sizeof(float), 0,
                            cudaMemcpyDeviceToDevice);

    dim3 block(32, 8);
    dim3 grid(WW / 32, HH / 8);
    sconv_kernel<<<grid, block>>>(out);
}

// round 13
// speedup vs baseline: 1.0406x; 1.0406x over previous
#include <cuda_runtime.h>
#include <cuda_fp16.h>

#define BB 2
#define CC 8
#define HH 512
#define WW 1024
#define OC 8
#define KY 3
#define KX 3
#define KK (KY*KX)
#define HW (HH*WW)

// fp16 transposed input: [b][pix] -> 8 channels packed in 16 bytes.
__device__ __align__(16) uint4 g_h[(size_t)BB * HW];
// staging for weight relayout [k][c][o]
__device__ __align__(16) float g_wstage[KK * CC * OC];

__constant__ __align__(16) float c_ws[KK * CC * OC]; // [k][c][o]
__constant__ __align__(16) float c_sb[OC];

// Two independent pixel chains per thread (MLP=16), streaming reads.
__global__ __launch_bounds__(256) void transpose_h2(const float* __restrict__ x) {
    int idx = blockIdx.x * 256 + threadIdx.x;   // over B*HW/2
    const int NHALF = BB * HW / 2;
    if (idx >= NHALF) return;
#pragma unroll
    for (int half = 0; half < 2; half++) {
        int id = idx + half * NHALF;
        int b = id >> 19;                        // /(H*W)
        int hw = id & (HW - 1);
        const float* xp = x + (size_t)b * CC * HW + hw;
        float p0 = __ldcs(xp + 0 * HW);
        float p1 = __ldcs(xp + 1 * HW);
        float p2 = __ldcs(xp + 2 * HW);
        float p3 = __ldcs(xp + 3 * HW);
        float p4 = __ldcs(xp + 4 * HW);
        float p5 = __ldcs(xp + 5 * HW);
        float p6 = __ldcs(xp + 6 * HW);
        float p7 = __ldcs(xp + 7 * HW);
        __half2 h0 = __floats2half2_rn(p0, p1);
        __half2 h1 = __floats2half2_rn(p2, p3);
        __half2 h2 = __floats2half2_rn(p4, p5);
        __half2 h3 = __floats2half2_rn(p6, p7);
        uint4 q;
        q.x = *reinterpret_cast<unsigned*>(&h0);
        q.y = *reinterpret_cast<unsigned*>(&h1);
        q.z = *reinterpret_cast<unsigned*>(&h2);
        q.w = *reinterpret_cast<unsigned*>(&h3);
        g_h[id] = q;
    }
}

__global__ void repack_w(const float* __restrict__ wgt) {
    int i = threadIdx.x; // 0..575
    if (i >= KK * CC * OC) return;
    int k = i >> 6;
    int c = (i >> 3) & 7;
    int o = i & 7;
    g_wstage[i] = wgt[(o * CC + c) * KK + k];
}

// atan2 with single fast division + Cephes poly. ~1e-7 rad error.
// Returns exactly +/-0 when y == 0 and x > 0 (relied on for the fx==0 path).
__device__ __forceinline__ float fast_atan2f(float y, float x) {
    float ay = fabsf(y), ax = fabsf(x);
    float n = fminf(ay, ax), d = fmaxf(ay, ax);
    bool big = n > 0.4142135624f * d;
    float num = big ? (n - d) : n;
    float den = big ? (n + d) : d;
    float t = __fdividef(num, den);
    float z = t * t;
    float p = fmaf(fmaf(fmaf(8.05374449538e-2f, z, -1.38776856032e-1f), z,
                        1.99777106478e-1f), z, -3.33329491539e-1f);
    float r = fmaf(p * z, t, t);
    if (big) r += 0.78539816339744831f;
    if (ay > ax) r = 1.57079632679489662f - r;
    if (x < 0.0f) r = 3.14159265358979323f - r;
    return copysignf(r, y);
}

__device__ __forceinline__ unsigned long long dup_f32x2(float f) {
    unsigned long long r;
    asm("mov.b64 %0, {%1, %1};" : "=l"(r) : "f"(f));
    return r;
}

__device__ __forceinline__ void ffma2(unsigned long long& acc,
                                      unsigned long long a, unsigned long long b) {
    asm("fma.rn.f32x2 %0, %1, %2, %0;" : "+l"(acc) : "l"(a), "l"(b));
}

__device__ __forceinline__ __half2 u2h2(unsigned u) { return *reinterpret_cast<__half2*>(&u); }

// 4-tap bilinear over 8 fp16 channels -> 8 fp32
__device__ __forceinline__ void bilin4(uint4 A, uint4 B, uint4 C, uint4 D,
                                       __half2 w00, __half2 w01, __half2 w10, __half2 w11,
                                       float* v) {
    const __half2* a = reinterpret_cast<const __half2*>(&A);
    const __half2* b = reinterpret_cast<const __half2*>(&B);
    const __half2* c = reinterpret_cast<const __half2*>(&C);
    const __half2* d = reinterpret_cast<const __half2*>(&D);
#pragma unroll
    for (int j = 0; j < 4; j++) {
        __half2 t = __hmul2(a[j], w00);
        t = __hfma2(b[j], w01, t);
        t = __hfma2(c[j], w10, t);
        t = __hfma2(d[j], w11, t);
        float2 f = __half22float2(t);
        v[2 * j]     = f.x;
        v[2 * j + 1] = f.y;
    }
}

// 2-tap (y only): fx == 0 exact path
__device__ __forceinline__ void bilin2(uint4 A, uint4 B,
                                       __half2 wy0, __half2 wy1, float* v) {
    const __half2* a = reinterpret_cast<const __half2*>(&A);
    const __half2* b = reinterpret_cast<const __half2*>(&B);
#pragma unroll
    for (int j = 0; j < 4; j++) {
        __half2 t = __hfma2(b[j], wy1, __hmul2(a[j], wy0));
        float2 f = __half22float2(t);
        v[2 * j]     = f.x;
        v[2 * j + 1] = f.y;
    }
}

// direct convert of one pixel (exact center tap)
__device__ __forceinline__ void cvt8(uint4 A, float* v) {
    const __half2* a = reinterpret_cast<const __half2*>(&A);
#pragma unroll
    for (int j = 0; j < 4; j++) {
        float2 f = __half22float2(a[j]);
        v[2 * j]     = f.x;
        v[2 * j + 1] = f.y;
    }
}

__global__ __launch_bounds__(256, 4) void sconv_kernel(float* __restrict__ out) {
    constexpr float PI_F = 3.14159265358979323846f;
    __shared__ __align__(16) int4  s_i[8][KK];   // {mxi, y0*W, y1*W, axis_flag}
    __shared__ __align__(16) uint4 s_hw[8][KK];  // half2 weights {w00,w01,w10,w11}

    int lane = threadIdx.x;
    int ty = threadIdx.y;
    int tid = ty * 32 + lane;

    // Per-(h,k) warp-uniform geometry + packed bilinear weights.
    if (tid < 8 * KK) {
        int tr = tid / KK;
        int k = tid - tr * KK;
        int h = blockIdx.y * 8 + tr;
        const float scale = PI_F / (float)HH;
        const float gx_scale = (float)WW / (2.0f * PI_F);
        const float gy_scale = (float)HH / PI_F;
        float po = PI_F * ((float)(2 * h + 1) * (0.5f / HH));
        float sp, cp;
        sincosf(po, &sp, &cp);
        float dx = (float)(k % KX - 1) * scale;
        float dy = (float)(k / KX - 1) * scale;
        float alpha = fmaf(cp, dy, sp);
        float gamma = fmaf(-sp, dy, cp);
        float r = sqrtf(fmaf(alpha, alpha, dx * dx));
        float pol = fast_atan2f(r, gamma);
        float phi = fast_atan2f(dx, alpha);
        float gy = pol * gy_scale - 0.5f;
        int iy0 = __float2int_rd(gy);
        float fy = gy - (float)iy0;
        int iy1 = min(iy0 + 1, HH - 1);
        iy0 = max(iy0, 0);
        float phi_px = phi * gx_scale;
        int mxi = __float2int_rd(phi_px);
        float fx = phi_px - (float)mxi;
        int axis = (phi_px == 0.0f) ? 1 : 0;
        float wx0 = 1.0f - fx, fy0 = 1.0f - fy;
        __half2 h00 = __float2half2_rn(wx0 * fy0);
        __half2 h01 = __float2half2_rn(fx * fy0);
        __half2 h10 = __float2half2_rn(wx0 * fy);
        __half2 h11 = __float2half2_rn(fx * fy);
        s_i[tr][k] = make_int4(mxi, iy0 * WW, iy1 * WW, axis);
        uint4 hw;
        hw.x = *reinterpret_cast<unsigned*>(&h00);
        hw.y = *reinterpret_cast<unsigned*>(&h01);
        hw.z = *reinterpret_cast<unsigned*>(&h10);
        hw.w = *reinterpret_cast<unsigned*>(&h11);
        s_hw[tr][k] = hw;
    }
    __syncthreads();

    int w = blockIdx.x * 32 + lane;
    int h = blockIdx.y * 8 + ty;

    unsigned long long a0[4], a1[4];
    const unsigned long long* sbp = reinterpret_cast<const unsigned long long*>(c_sb);
#pragma unroll
    for (int j = 0; j < 4; j++) { a0[j] = sbp[j]; a1[j] = sbp[j]; }

    const ulonglong2* wsp = reinterpret_cast<const ulonglong2*>(c_ws);

#pragma unroll
    for (int k = 0; k < KK; k++) {
        float v0[8], v1[8];

        if (k == 4) {
            // center tap: exact identity sample
            int i = h * WW + w;
            cvt8(g_h[i], v0);
            cvt8(g_h[HW + i], v1);
        } else {
            int4 si = s_i[ty][k];
            uint4 hw = s_hw[ty][k];
            int ix0 = (w + si.x) & (WW - 1);
            bool axis = ((k == 1) || (k == 7)) && si.w;
            if (axis) {
                bilin2(g_h[si.y + ix0], g_h[si.z + ix0], u2h2(hw.x), u2h2(hw.z), v0);
                bilin2(g_h[HW + si.y + ix0], g_h[HW + si.z + ix0], u2h2(hw.x), u2h2(hw.z), v1);
            } else {
                int ix1 = (ix0 + 1) & (WW - 1);
                bilin4(g_h[si.y + ix0], g_h[si.y + ix1],
                       g_h[si.z + ix0], g_h[si.z + ix1],
                       u2h2(hw.x), u2h2(hw.y), u2h2(hw.z), u2h2(hw.w), v0);
                bilin4(g_h[HW + si.y + ix0], g_h[HW + si.y + ix1],
                       g_h[HW + si.z + ix0], g_h[HW + si.z + ix1],
                       u2h2(hw.x), u2h2(hw.y), u2h2(hw.z), u2h2(hw.w), v1);
            }
        }

        const ulonglong2* wk = wsp + k * 16;
#pragma unroll
        for (int c = 0; c < CC; c++) {
            ulonglong2 wa = wk[c * 2 + 0]; // (o0,o1),(o2,o3)
            ulonglong2 wb = wk[c * 2 + 1]; // (o4,o5),(o6,o7)
            unsigned long long vd0 = dup_f32x2(v0[c]);
            unsigned long long vd1 = dup_f32x2(v1[c]);
            ffma2(a0[0], vd0, wa.x);
            ffma2(a0[1], vd0, wa.y);
            ffma2(a0[2], vd0, wb.x);
            ffma2(a0[3], vd0, wb.y);
            ffma2(a1[0], vd1, wa.x);
            ffma2(a1[1], vd1, wa.y);
            ffma2(a1[2], vd1, wb.x);
            ffma2(a1[3], vd1, wb.y);
        }
    }

#pragma unroll
    for (int j = 0; j < 4; j++) {
        float l0, h0, l1, h1;
        asm("mov.b64 {%0, %1}, %2;" : "=f"(l0), "=f"(h0) : "l"(a0[j]));
        asm("mov.b64 {%0, %1}, %2;" : "=f"(l1), "=f"(h1) : "l"(a1[j]));
        int o = 2 * j;
        out[(size_t)((0 * OC + o) * HH + h) * WW + w]     = l0;
        out[(size_t)((0 * OC + o + 1) * HH + h) * WW + w] = h0;
        out[(size_t)((1 * OC + o) * HH + h) * WW + w]     = l1;
        out[(size_t)((1 * OC + o + 1) * HH + h) * WW + w] = h1;
    }
}

extern "C" void kernel_launch(void* const* d_in, const int* in_sizes, int n_in,
                              void* d_out, int out_size) {
    const float* x = (const float*)d_in[0];
    const float* wgt = (const float*)d_in[1];
    const float* bias = (const float*)d_in[2];
    float* out = (float*)d_out;

    int nhalf = BB * HW / 2;
    transpose_h2<<<(nhalf + 255) / 256, 256>>>(x);

    repack_w<<<1, KK * CC * OC>>>(wgt);

    // Resolve the staging buffer's real device address (query only — no alloc).
    void* wstage_dev = nullptr;
    cudaGetSymbolAddress(&wstage_dev, g_wstage);

    // D2D memcpy nodes (graph-capturable, allocation-free)
    cudaMemcpyToSymbolAsync(c_ws, wstage_dev, KK * CC * OC * sizeof(float), 0,
                            cudaMemcpyDeviceToDevice);
    cudaMemcpyToSymbolAsync(c_sb, bias, OC * sizeof(float), 0,
                            cudaMemcpyDeviceToDevice);

    dim3 block(32, 8);
    dim3 grid(WW / 32, HH / 8);
    sconv_kernel<<<grid, block>>>(out);
}

// round 14
// speedup vs baseline: 1.1130x; 1.0695x over previous
#include <cuda_runtime.h>
#include <cuda_fp16.h>

#define BB 2
#define CC 8
#define HH 512
#define WW 1024
#define OC 8
#define KY 3
#define KX 3
#define KK (KY*KX)
#define HW (HH*WW)

// fp16 transposed input: [b][pix] -> 8 channels packed in 16 bytes.
__device__ __align__(16) uint4 g_h[(size_t)BB * HW];
// staging for weight relayout [k][c][o]
__device__ __align__(16) float g_wstage[KK * CC * OC];

__constant__ __align__(16) float c_ws[KK * CC * OC]; // [k][c][o]

// Two independent pixel chains per thread (MLP=16), streaming reads.
// Block 0 additionally repacks the conv weights into g_wstage.
__global__ __launch_bounds__(256) void transpose_h2(const float* __restrict__ x,
                                                    const float* __restrict__ wgt) {
    int idx = blockIdx.x * 256 + threadIdx.x;   // over B*HW/2
    const int NHALF = BB * HW / 2;

    if (blockIdx.x < 3) {
        int i = blockIdx.x * 256 + threadIdx.x; // 0..767 covers 576
        if (i < KK * CC * OC) {
            int k = i >> 6;
            int c = (i >> 3) & 7;
            int o = i & 7;
            g_wstage[i] = wgt[(o * CC + c) * KK + k];
        }
    }

    if (idx >= NHALF) return;
#pragma unroll
    for (int half = 0; half < 2; half++) {
        int id = idx + half * NHALF;
        int b = id >> 19;                        // /(H*W)
        int hw = id & (HW - 1);
        const float* xp = x + (size_t)b * CC * HW + hw;
        float p0 = __ldcs(xp + 0 * HW);
        float p1 = __ldcs(xp + 1 * HW);
        float p2 = __ldcs(xp + 2 * HW);
        float p3 = __ldcs(xp + 3 * HW);
        float p4 = __ldcs(xp + 4 * HW);
        float p5 = __ldcs(xp + 5 * HW);
        float p6 = __ldcs(xp + 6 * HW);
        float p7 = __ldcs(xp + 7 * HW);
        __half2 h0 = __floats2half2_rn(p0, p1);
        __half2 h1 = __floats2half2_rn(p2, p3);
        __half2 h2 = __floats2half2_rn(p4, p5);
        __half2 h3 = __floats2half2_rn(p6, p7);
        uint4 q;
        q.x = *reinterpret_cast<unsigned*>(&h0);
        q.y = *reinterpret_cast<unsigned*>(&h1);
        q.z = *reinterpret_cast<unsigned*>(&h2);
        q.w = *reinterpret_cast<unsigned*>(&h3);
        g_h[id] = q;
    }
}

// atan2 with single fast division + Cephes poly. ~1e-7 rad error.
// Returns exactly +/-0 when y == 0 and x > 0 (relied on for the fx==0 path).
__device__ __forceinline__ float fast_atan2f(float y, float x) {
    float ay = fabsf(y), ax = fabsf(x);
    float n = fminf(ay, ax), d = fmaxf(ay, ax);
    bool big = n > 0.4142135624f * d;
    float num = big ? (n - d) : n;
    float den = big ? (n + d) : d;
    float t = __fdividef(num, den);
    float z = t * t;
    float p = fmaf(fmaf(fmaf(8.05374449538e-2f, z, -1.38776856032e-1f), z,
                        1.99777106478e-1f), z, -3.33329491539e-1f);
    float r = fmaf(p * z, t, t);
    if (big) r += 0.78539816339744831f;
    if (ay > ax) r = 1.57079632679489662f - r;
    if (x < 0.0f) r = 3.14159265358979323f - r;
    return copysignf(r, y);
}

__device__ __forceinline__ unsigned long long dup_f32x2(float f) {
    unsigned long long r;
    asm("mov.b64 %0, {%1, %1};" : "=l"(r) : "f"(f));
    return r;
}

__device__ __forceinline__ void ffma2(unsigned long long& acc,
                                      unsigned long long a, unsigned long long b) {
    asm("fma.rn.f32x2 %0, %1, %2, %0;" : "+l"(acc) : "l"(a), "l"(b));
}

__device__ __forceinline__ __half2 u2h2(unsigned u) { return *reinterpret_cast<__half2*>(&u); }

// 4-tap bilinear over 8 fp16 channels -> 8 fp32
__device__ __forceinline__ void bilin4(uint4 A, uint4 B, uint4 C, uint4 D,
                                       __half2 w00, __half2 w01, __half2 w10, __half2 w11,
                                       float* v) {
    const __half2* a = reinterpret_cast<const __half2*>(&A);
    const __half2* b = reinterpret_cast<const __half2*>(&B);
    const __half2* c = reinterpret_cast<const __half2*>(&C);
    const __half2* d = reinterpret_cast<const __half2*>(&D);
#pragma unroll
    for (int j = 0; j < 4; j++) {
        __half2 t = __hmul2(a[j], w00);
        t = __hfma2(b[j], w01, t);
        t = __hfma2(c[j], w10, t);
        t = __hfma2(d[j], w11, t);
        float2 f = __half22float2(t);
        v[2 * j]     = f.x;
        v[2 * j + 1] = f.y;
    }
}

// 2-tap (y only): fx == 0 exact path
__device__ __forceinline__ void bilin2(uint4 A, uint4 B,
                                       __half2 wy0, __half2 wy1, float* v) {
    const __half2* a = reinterpret_cast<const __half2*>(&A);
    const __half2* b = reinterpret_cast<const __half2*>(&B);
#pragma unroll
    for (int j = 0; j < 4; j++) {
        __half2 t = __hfma2(b[j], wy1, __hmul2(a[j], wy0));
        float2 f = __half22float2(t);
        v[2 * j]     = f.x;
        v[2 * j + 1] = f.y;
    }
}

// direct convert of one pixel (exact center tap)
__device__ __forceinline__ void cvt8(uint4 A, float* v) {
    const __half2* a = reinterpret_cast<const __half2*>(&A);
#pragma unroll
    for (int j = 0; j < 4; j++) {
        float2 f = __half22float2(a[j]);
        v[2 * j]     = f.x;
        v[2 * j + 1] = f.y;
    }
}

__global__ __launch_bounds__(256, 4) void sconv_kernel(const float* __restrict__ bias,
                                                       float* __restrict__ out) {
    constexpr float PI_F = 3.14159265358979323846f;
    __shared__ __align__(16) int4  s_i[8][KK];   // {mxi, y0*W, y1*W, axis_flag}
    __shared__ __align__(16) uint4 s_hw[8][KK];  // half2 weights {w00,w01,w10,w11}

    int lane = threadIdx.x;
    int ty = threadIdx.y;
    int tid = ty * 32 + lane;

    // Per-(h,k) warp-uniform geometry + packed bilinear weights.
    if (tid < 8 * KK) {
        int tr = tid / KK;
        int k = tid - tr * KK;
        int h = blockIdx.y * 8 + tr;
        const float scale = PI_F / (float)HH;
        const float gx_scale = (float)WW / (2.0f * PI_F);
        const float gy_scale = (float)HH / PI_F;
        float po = PI_F * ((float)(2 * h + 1) * (0.5f / HH));
        float sp, cp;
        sincosf(po, &sp, &cp);
        float dx = (float)(k % KX - 1) * scale;
        float dy = (float)(k / KX - 1) * scale;
        float alpha = fmaf(cp, dy, sp);
        float gamma = fmaf(-sp, dy, cp);
        float r = sqrtf(fmaf(alpha, alpha, dx * dx));
        float pol = fast_atan2f(r, gamma);
        float phi = fast_atan2f(dx, alpha);
        float gy = pol * gy_scale - 0.5f;
        int iy0 = __float2int_rd(gy);
        float fy = gy - (float)iy0;
        int iy1 = min(iy0 + 1, HH - 1);
        iy0 = max(iy0, 0);
        float phi_px = phi * gx_scale;
        int mxi = __float2int_rd(phi_px);
        float fx = phi_px - (float)mxi;
        int axis = (phi_px == 0.0f) ? 1 : 0;
        float wx0 = 1.0f - fx, fy0 = 1.0f - fy;
        __half2 h00 = __float2half2_rn(wx0 * fy0);
        __half2 h01 = __float2half2_rn(fx * fy0);
        __half2 h10 = __float2half2_rn(wx0 * fy);
        __half2 h11 = __float2half2_rn(fx * fy);
        s_i[tr][k] = make_int4(mxi, iy0 * WW, iy1 * WW, axis);
        uint4 hw;
        hw.x = *reinterpret_cast<unsigned*>(&h00);
        hw.y = *reinterpret_cast<unsigned*>(&h01);
        hw.z = *reinterpret_cast<unsigned*>(&h10);
        hw.w = *reinterpret_cast<unsigned*>(&h11);
        s_hw[tr][k] = hw;
    }
    __syncthreads();

    int w = blockIdx.x * 32 + lane;
    int h = blockIdx.y * 8 + ty;

    // bias via read-only cache (uniform address -> L1 broadcast)
    unsigned long long a0[4], a1[4];
    const ulonglong2* bp = reinterpret_cast<const ulonglong2*>(bias);
    ulonglong2 b01 = __ldg(bp);
    ulonglong2 b23 = __ldg(bp + 1);
    a0[0] = b01.x; a0[1] = b01.y; a0[2] = b23.x; a0[3] = b23.y;
    a1[0] = b01.x; a1[1] = b01.y; a1[2] = b23.x; a1[3] = b23.y;

    const ulonglong2* wsp = reinterpret_cast<const ulonglong2*>(c_ws);

#pragma unroll
    for (int k = 0; k < KK; k++) {
        float v0[8], v1[8];

        if (k == 4) {
            // center tap: exact identity sample
            int i = h * WW + w;
            cvt8(g_h[i], v0);
            cvt8(g_h[HW + i], v1);
        } else {
            int4 si = s_i[ty][k];
            uint4 hw = s_hw[ty][k];
            int ix0 = (w + si.x) & (WW - 1);
            bool axis = ((k == 1) || (k == 7)) && si.w;
            if (axis) {
                bilin2(g_h[si.y + ix0], g_h[si.z + ix0], u2h2(hw.x), u2h2(hw.z), v0);
                bilin2(g_h[HW + si.y + ix0], g_h[HW + si.z + ix0], u2h2(hw.x), u2h2(hw.z), v1);
            } else {
                int ix1 = (ix0 + 1) & (WW - 1);
                bilin4(g_h[si.y + ix0], g_h[si.y + ix1],
                       g_h[si.z + ix0], g_h[si.z + ix1],
                       u2h2(hw.x), u2h2(hw.y), u2h2(hw.z), u2h2(hw.w), v0);
                bilin4(g_h[HW + si.y + ix0], g_h[HW + si.y + ix1],
                       g_h[HW + si.z + ix0], g_h[HW + si.z + ix1],
                       u2h2(hw.x), u2h2(hw.y), u2h2(hw.z), u2h2(hw.w), v1);
            }
        }

        const ulonglong2* wk = wsp + k * 16;
#pragma unroll
        for (int c = 0; c < CC; c++) {
            ulonglong2 wa = wk[c * 2 + 0]; // (o0,o1),(o2,o3)
            ulonglong2 wb = wk[c * 2 + 1]; // (o4,o5),(o6,o7)
            unsigned long long vd0 = dup_f32x2(v0[c]);
            unsigned long long vd1 = dup_f32x2(v1[c]);
            ffma2(a0[0], vd0, wa.x);
            ffma2(a0[1], vd0, wa.y);
            ffma2(a0[2], vd0, wb.x);
            ffma2(a0[3], vd0, wb.y);
            ffma2(a1[0], vd1, wa.x);
            ffma2(a1[1], vd1, wa.y);
            ffma2(a1[2], vd1, wb.x);
            ffma2(a1[3], vd1, wb.y);
        }
    }

#pragma unroll
    for (int j = 0; j < 4; j++) {
        float l0, h0, l1, h1;
        asm("mov.b64 {%0, %1}, %2;" : "=f"(l0), "=f"(h0) : "l"(a0[j]));
        asm("mov.b64 {%0, %1}, %2;" : "=f"(l1), "=f"(h1) : "l"(a1[j]));
        int o = 2 * j;
        out[(size_t)((0 * OC + o) * HH + h) * WW + w]     = l0;
        out[(size_t)((0 * OC + o + 1) * HH + h) * WW + w] = h0;
        out[(size_t)((1 * OC + o) * HH + h) * WW + w]     = l1;
        out[(size_t)((1 * OC + o + 1) * HH + h) * WW + w] = h1;
    }
}

extern "C" void kernel_launch(void* const* d_in, const int* in_sizes, int n_in,
                              void* d_out, int out_size) {
    const float* x = (const float*)d_in[0];
    const float* wgt = (const float*)d_in[1];
    const float* bias = (const float*)d_in[2];
    float* out = (float*)d_out;

    int nhalf = BB * HW / 2;
    transpose_h2<<<(nhalf + 255) / 256, 256>>>(x, wgt);

    // Resolve the staging buffer's real device address (query only — no alloc).
    void* wstage_dev = nullptr;
    cudaGetSymbolAddress(&wstage_dev, g_wstage);

    // Single D2D memcpy node into constant bank (graph-capturable)
    cudaMemcpyToSymbolAsync(c_ws, wstage_dev, KK * CC * OC * sizeof(float), 0,
                            cudaMemcpyDeviceToDevice);

    dim3 block(32, 8);
    dim3 grid(WW / 32, HH / 8);
    sconv_kernel<<<grid, block>>>(bias, out);
}

// round 15
// speedup vs baseline: 1.1603x; 1.0425x over previous
#include <cuda_runtime.h>
#include <cuda_fp16.h>

#define BB 2
#define CC 8
#define HH 512
#define WW 1024
#define OC 8
#define KY 3
#define KX 3
#define KK (KY*KX)
#define HW (HH*WW)

// fp16 transposed input: [b][pix] -> 8 channels packed in 16 bytes.
__device__ __align__(16) uint4 g_h[(size_t)BB * HW];
// per-lane B fragments for mma.m16n8k8: g_wfrag[tap*32 + lane] =
//   half2( W[tap][2*(lane%4)][lane/4], W[tap][2*(lane%4)+1][lane/4] )
__device__ unsigned g_wfrag[KK * 32];

// Two independent pixel chains per thread (MLP=16), streaming reads.
// First two blocks additionally pack the weight fragments.
__global__ __launch_bounds__(256) void transpose_h2(const float* __restrict__ x,
                                                    const float* __restrict__ wgt) {
    int idx = blockIdx.x * 256 + threadIdx.x;   // over B*HW/2
    const int NHALF = BB * HW / 2;

    if (idx < KK * 32) {
        int tap = idx >> 5;
        int l = idx & 31;
        int g = l >> 2;        // output channel o
        int tg = l & 3;        // quad id -> input channels 2tg, 2tg+1
        float lo = wgt[(g * CC + 2 * tg) * KK + tap];
        float hi = wgt[(g * CC + 2 * tg + 1) * KK + tap];
        __half2 hh = __floats2half2_rn(lo, hi);
        g_wfrag[idx] = *reinterpret_cast<unsigned*>(&hh);
    }

    if (idx >= NHALF) return;
#pragma unroll
    for (int half = 0; half < 2; half++) {
        int id = idx + half * NHALF;
        int b = id >> 19;                        // /(H*W)
        int hw = id & (HW - 1);
        const float* xp = x + (size_t)b * CC * HW + hw;
        float p0 = __ldcs(xp + 0 * HW);
        float p1 = __ldcs(xp + 1 * HW);
        float p2 = __ldcs(xp + 2 * HW);
        float p3 = __ldcs(xp + 3 * HW);
        float p4 = __ldcs(xp + 4 * HW);
        float p5 = __ldcs(xp + 5 * HW);
        float p6 = __ldcs(xp + 6 * HW);
        float p7 = __ldcs(xp + 7 * HW);
        __half2 h0 = __floats2half2_rn(p0, p1);
        __half2 h1 = __floats2half2_rn(p2, p3);
        __half2 h2 = __floats2half2_rn(p4, p5);
        __half2 h3 = __floats2half2_rn(p6, p7);
        uint4 q;
        q.x = *reinterpret_cast<unsigned*>(&h0);
        q.y = *reinterpret_cast<unsigned*>(&h1);
        q.z = *reinterpret_cast<unsigned*>(&h2);
        q.w = *reinterpret_cast<unsigned*>(&h3);
        g_h[id] = q;
    }
}

// atan2 with single fast division + Cephes poly. ~1e-7 rad error.
// Returns exactly +/-0 when y == 0 and x > 0 (relied on for the fx==0 path).
__device__ __forceinline__ float fast_atan2f(float y, float x) {
    float ay = fabsf(y), ax = fabsf(x);
    float n = fminf(ay, ax), d = fmaxf(ay, ax);
    bool big = n > 0.4142135624f * d;
    float num = big ? (n - d) : n;
    float den = big ? (n + d) : d;
    float t = __fdividef(num, den);
    float z = t * t;
    float p = fmaf(fmaf(fmaf(8.05374449538e-2f, z, -1.38776856032e-1f), z,
                        1.99777106478e-1f), z, -3.33329491539e-1f);
    float r = fmaf(p * z, t, t);
    if (big) r += 0.78539816339744831f;
    if (ay > ax) r = 1.57079632679489662f - r;
    if (x < 0.0f) r = 3.14159265358979323f - r;
    return copysignf(r, y);
}

__device__ __forceinline__ __half2 u2h2(unsigned u) { return *reinterpret_cast<__half2*>(&u); }

// 4-tap bilinear over 8 fp16 channels, result kept as packed half2 x4 (uint4)
__device__ __forceinline__ uint4 blend4h(uint4 A, uint4 B, uint4 C, uint4 D,
                                         __half2 w00, __half2 w01, __half2 w10, __half2 w11) {
    const __half2* a = reinterpret_cast<const __half2*>(&A);
    const __half2* b = reinterpret_cast<const __half2*>(&B);
    const __half2* c = reinterpret_cast<const __half2*>(&C);
    const __half2* d = reinterpret_cast<const __half2*>(&D);
    uint4 o;
    unsigned* op = &o.x;
#pragma unroll
    for (int j = 0; j < 4; j++) {
        __half2 t = __hmul2(a[j], w00);
        t = __hfma2(b[j], w01, t);
        t = __hfma2(c[j], w10, t);
        t = __hfma2(d[j], w11, t);
        op[j] = *reinterpret_cast<unsigned*>(&t);
    }
    return o;
}

// 2-tap (y only): fx == 0 exact path
__device__ __forceinline__ uint4 blend2h(uint4 A, uint4 B, __half2 wy0, __half2 wy1) {
    const __half2* a = reinterpret_cast<const __half2*>(&A);
    const __half2* b = reinterpret_cast<const __half2*>(&B);
    uint4 o;
    unsigned* op = &o.x;
#pragma unroll
    for (int j = 0; j < 4; j++) {
        __half2 t = __hfma2(b[j], wy1, __hmul2(a[j], wy0));
        op[j] = *reinterpret_cast<unsigned*>(&t);
    }
    return o;
}

__global__ __launch_bounds__(256, 3) void sconv_kernel(const float* __restrict__ bias,
                                                       float* __restrict__ out) {
    constexpr float PI_F = 3.14159265358979323846f;
    __shared__ __align__(16) int4  s_i[8][KK];   // {mxi, y0*W, y1*W, axis_flag}
    __shared__ __align__(16) uint4 s_hw[8][KK];  // half2 weights {w00,w01,w10,w11}
    __shared__ __align__(16) uint4 s_v[8][2][32]; // [warp][batch][pixel] fp16 ch0..7

    int lane = threadIdx.x;
    int ty = threadIdx.y;
    int tid = ty * 32 + lane;

    // Per-(h,k) warp-uniform geometry + packed bilinear weights.
    if (tid < 8 * KK) {
        int tr = tid / KK;
        int k = tid - tr * KK;
        int h = blockIdx.y * 8 + tr;
        const float scale = PI_F / (float)HH;
        const float gx_scale = (float)WW / (2.0f * PI_F);
        const float gy_scale = (float)HH / PI_F;
        float po = PI_F * ((float)(2 * h + 1) * (0.5f / HH));
        float sp, cp;
        sincosf(po, &sp, &cp);
        float dx = (float)(k % KX - 1) * scale;
        float dy = (float)(k / KX - 1) * scale;
        float alpha = fmaf(cp, dy, sp);
        float gamma = fmaf(-sp, dy, cp);
        float r = sqrtf(fmaf(alpha, alpha, dx * dx));
        float pol = fast_atan2f(r, gamma);
        float phi = fast_atan2f(dx, alpha);
        float gy = pol * gy_scale - 0.5f;
        int iy0 = __float2int_rd(gy);
        float fy = gy - (float)iy0;
        int iy1 = min(iy0 + 1, HH - 1);
        iy0 = max(iy0, 0);
        float phi_px = phi * gx_scale;
        int mxi = __float2int_rd(phi_px);
        float fx = phi_px - (float)mxi;
        int axis = (phi_px == 0.0f) ? 1 : 0;
        float wx0 = 1.0f - fx, fy0 = 1.0f - fy;
        __half2 h00 = __float2half2_rn(wx0 * fy0);
        __half2 h01 = __float2half2_rn(fx * fy0);
        __half2 h10 = __float2half2_rn(wx0 * fy);
        __half2 h11 = __float2half2_rn(fx * fy);
        s_i[tr][k] = make_int4(mxi, iy0 * WW, iy1 * WW, axis);
        uint4 hw;
        hw.x = *reinterpret_cast<unsigned*>(&h00);
        hw.y = *reinterpret_cast<unsigned*>(&h01);
        hw.z = *reinterpret_cast<unsigned*>(&h10);
        hw.w = *reinterpret_cast<unsigned*>(&h11);
        s_hw[tr][k] = hw;
    }
    __syncthreads();

    int wb = blockIdx.x * 32;
    int w = wb + lane;
    int h = blockIdx.y * 8 + ty;
    int gid = lane >> 2;
    int tig = lane & 3;

    // Per-tap B fragments (coalesced one-time load)
    unsigned wf[KK];
#pragma unroll
    for (int t = 0; t < KK; t++) wf[t] = __ldg(&g_wfrag[t * 32 + lane]);

    // Accumulators: [batch][mtile][4], bias folded in.
    float bv0 = __ldg(&bias[2 * tig]);
    float bv1 = __ldg(&bias[2 * tig + 1]);
    float acc[2][2][4];
#pragma unroll
    for (int b = 0; b < 2; b++)
#pragma unroll
        for (int mt = 0; mt < 2; mt++) {
            acc[b][mt][0] = bv0; acc[b][mt][1] = bv1;
            acc[b][mt][2] = bv0; acc[b][mt][3] = bv1;
        }

    unsigned ldbase = (unsigned)__cvta_generic_to_shared(&s_v[ty][0][0]);

#pragma unroll
    for (int k = 0; k < KK; k++) {
        uint4 v0, v1;
        if (k == 4) {
            int i = h * WW + w;
            v0 = g_h[i];
            v1 = g_h[HW + i];
        } else {
            int4 si = s_i[ty][k];
            uint4 hw = s_hw[ty][k];
            int ix0 = (w + si.x) & (WW - 1);
            bool axis = ((k == 1) || (k == 7)) && si.w;
            if (axis) {
                v0 = blend2h(g_h[si.y + ix0], g_h[si.z + ix0], u2h2(hw.x), u2h2(hw.z));
                v1 = blend2h(g_h[HW + si.y + ix0], g_h[HW + si.z + ix0], u2h2(hw.x), u2h2(hw.z));
            } else {
                int ix1 = (ix0 + 1) & (WW - 1);
                v0 = blend4h(g_h[si.y + ix0], g_h[si.y + ix1],
                             g_h[si.z + ix0], g_h[si.z + ix1],
                             u2h2(hw.x), u2h2(hw.y), u2h2(hw.z), u2h2(hw.w));
                v1 = blend4h(g_h[HW + si.y + ix0], g_h[HW + si.y + ix1],
                             g_h[HW + si.z + ix0], g_h[HW + si.z + ix1],
                             u2h2(hw.x), u2h2(hw.y), u2h2(hw.z), u2h2(hw.w));
            }
        }

        __syncwarp();
        s_v[ty][0][lane] = v0;
        s_v[ty][1][lane] = v1;
        __syncwarp();

#pragma unroll
        for (int b = 0; b < 2; b++) {
#pragma unroll
            for (int mt = 0; mt < 2; mt++) {
                unsigned addr = ldbase + (unsigned)((b * 32 + mt * 16 + (lane & 15)) * 16);
                unsigned a0, a1;
                asm volatile("ldmatrix.sync.aligned.m8n8.x2.shared.b16 {%0,%1}, [%2];"
                             : "=r"(a0), "=r"(a1) : "r"(addr));
                asm volatile("mma.sync.aligned.m16n8k8.row.col.f32.f16.f16.f32 "
                             "{%0,%1,%2,%3}, {%4,%5}, {%6}, {%0,%1,%2,%3};"
                             : "+f"(acc[b][mt][0]), "+f"(acc[b][mt][1]),
                               "+f"(acc[b][mt][2]), "+f"(acc[b][mt][3])
                             : "r"(a0), "r"(a1), "r"(wf[k]));
            }
        }
    }

    // Epilogue: D[row=pixel][col=o]; thread holds pixels gid, gid+8 and o = 2tig, 2tig+1
#pragma unroll
    for (int b = 0; b < 2; b++)
#pragma unroll
        for (int mt = 0; mt < 2; mt++) {
            int wq = wb + mt * 16 + gid;
            size_t base0 = ((size_t)(b * OC + 2 * tig) * HH + h) * WW;
            size_t base1 = ((size_t)(b * OC + 2 * tig + 1) * HH + h) * WW;
            out[base0 + wq]     = acc[b][mt][0];
            out[base1 + wq]     = acc[b][mt][1];
            out[base0 + wq + 8] = acc[b][mt][2];
            out[base1 + wq + 8] = acc[b][mt][3];
        }
}

extern "C" void kernel_launch(void* const* d_in, const int* in_sizes, int n_in,
                              void* d_out, int out_size) {
    const float* x = (const float*)d_in[0];
    const float* wgt = (const float*)d_in[1];
    const float* bias = (const float*)d_in[2];
    float* out = (float*)d_out;

    int nhalf = BB * HW / 2;
    transpose_h2<<<(nhalf + 255) / 256, 256>>>(x, wgt);

    dim3 block(32, 8);
    dim3 grid(WW / 32, HH / 8);
    sconv_kernel<<<grid, block>>>(bias, out);
}